// round 7
// baseline (speedup 1.0000x reference)
#include <cuda_runtime.h>
#include <float.h>

#define QD 8192   // QUANT_DIM
#define ED 512    // EMBED_DIM
#define NT 8192   // N_TOKENS
#define CAP 64    // per-warp candidate capacity (overflow -> serial fallback)
#define WPB 8     // warps per block

// Scratch: weight.T [QD, ED] = 16 MB. Static __device__ global (no alloc).
__device__ float g_wT[(size_t)QD * ED];

// ---------------------------------------------------------------------------
// Kernel 1: tiled transpose weight[ED, QD] -> g_wT[QD, ED]
// ---------------------------------------------------------------------------
__global__ void transpose_kernel(const float* __restrict__ w) {
    __shared__ float tile[32][33];
    int qx = blockIdx.x * 32 + threadIdx.x;
    int ey = blockIdx.y * 32 + threadIdx.y;
#pragma unroll
    for (int j = 0; j < 32; j += 8)
        tile[threadIdx.y + j][threadIdx.x] = w[(size_t)(ey + j) * QD + qx];
    __syncthreads();
    int ex = blockIdx.y * 32 + threadIdx.x;
    int qy = blockIdx.x * 32 + threadIdx.y;
#pragma unroll
    for (int j = 0; j < 32; j += 8)
        g_wT[(size_t)(qy + j) * ED + ex] = tile[threadIdx.x][threadIdx.y + j];
}

// Strict total order lex(value desc, index asc) — matches jax.lax.top_k ties.
__device__ __forceinline__ bool lexgt(float av, int ai, float bv, int bi) {
    return (av > bv) || (av == bv && ai < bi);
}

// ---------------------------------------------------------------------------
// Kernel 2: warp-per-token top-8 + gather. NO block barriers.
// ---------------------------------------------------------------------------
__global__ __launch_bounds__(256) void topk_gather_kernel(
    const float* __restrict__ x, float* __restrict__ out) {
    const int lane = threadIdx.x & 31;
    const int wrp  = threadIdx.x >> 5;
    const int n    = blockIdx.x * WPB + wrp;

    __shared__ int   s_cnt[WPB];
    __shared__ float s_cv[WPB][CAP];
    __shared__ int   s_ci[WPB][CAP];

    if (lane == 0) s_cnt[wrp] = 0;
    __syncwarp();

    const float4* xr = reinterpret_cast<const float4*>(x + (size_t)n * QD);

    // ---- Phase 1: stream 256 elems/thread (64 float4), pure FMNMX.
    // Keep 8 group maxima (32 elems each) for the rescan.
    float gm[8];
#pragma unroll
    for (int g = 0; g < 8; g++) {
        float4 v[8];
#pragma unroll
        for (int c = 0; c < 8; c++)
            v[c] = __ldcs(&xr[(g * 8 + c) * 32 + lane]);  // evict-first stream
        float m = fmaxf(fmaxf(v[0].x, v[0].y), fmaxf(v[0].z, v[0].w));
#pragma unroll
        for (int c = 1; c < 8; c++)
            m = fmaxf(m, fmaxf(fmaxf(v[c].x, v[c].y), fmaxf(v[c].z, v[c].w)));
        gm[g] = m;
    }
    float mv = fmaxf(fmaxf(fmaxf(gm[0], gm[1]), fmaxf(gm[2], gm[3])),
                     fmaxf(fmaxf(gm[4], gm[5]), fmaxf(gm[6], gm[7])));

    // ---- Phase 2: warp bitonic sort (ascending) of the 32 lane maxima.
    // T8 = 8th largest = lane 24. The top-8 lane maxima are 8 distinct
    // elements >= T8, so every true top-8 element satisfies v >= T8.
    float sv = mv;
#pragma unroll
    for (int k = 2; k <= 32; k <<= 1) {
#pragma unroll
        for (int j = k >> 1; j > 0; j >>= 1) {
            float o = __shfl_xor_sync(0xffffffffu, sv, j);
            bool up    = ((lane & k) == 0);
            bool lower = ((lane & j) == 0);
            sv = (up == lower) ? fminf(sv, o) : fmaxf(sv, o);
        }
    }
    const float T8 = __shfl_sync(0xffffffffu, sv, 24);

    // ---- Phase 3: rescan triggered groups (expected ~2-3 lanes total),
    // reload from L2, push candidates to the per-warp buffer.
#pragma unroll
    for (int g = 0; g < 8; g++) {
        if (gm[g] >= T8) {
#pragma unroll
            for (int c = 0; c < 8; c++) {
                float4 a = __ldg(&xr[(g * 8 + c) * 32 + lane]);
                int base = 4 * ((g * 8 + c) * 32 + lane);
                float va[4] = {a.x, a.y, a.z, a.w};
#pragma unroll
                for (int j = 0; j < 4; j++) {
                    if (va[j] >= T8) {
                        int pos = atomicAdd(&s_cnt[wrp], 1);
                        if (pos < CAP) { s_cv[wrp][pos] = va[j]; s_ci[wrp][pos] = base + j; }
                    }
                }
            }
        }
    }
    __syncwarp();
    const int C = s_cnt[wrp];   // >= 8 guaranteed

    int idx[8];
    if (C <= CAP) {
        // ---- Phase 4: exact lex top-8 over candidates (warp-local).
        float tv[8]; int ti[8];
#pragma unroll
        for (int r = 0; r < 8; r++) { tv[r] = -FLT_MAX; ti[r] = 0x7FFFFFFF; }
        for (int i = lane; i < C; i += 32) {
            float v = s_cv[wrp][i]; int id = s_ci[wrp][i];
            if (lexgt(v, id, tv[7], ti[7])) {
                tv[7] = v; ti[7] = id;
#pragma unroll
                for (int p = 7; p > 0; p--) {
                    if (lexgt(tv[p], ti[p], tv[p - 1], ti[p - 1])) {
                        float fv = tv[p]; tv[p] = tv[p - 1]; tv[p - 1] = fv;
                        int   fi = ti[p]; ti[p] = ti[p - 1]; ti[p - 1] = fi;
                    }
                }
            }
        }
        __syncwarp();
        // 5 xor-shuffle bitonic merges with lex order -> all lanes identical.
#pragma unroll
        for (int s = 1; s < 32; s <<= 1) {
            float pv[8]; int pi[8];
#pragma unroll
            for (int r = 0; r < 8; r++) {
                pv[r] = __shfl_xor_sync(0xffffffffu, tv[r], s);
                pi[r] = __shfl_xor_sync(0xffffffffu, ti[r], s);
            }
            float L[8]; int Li[8];
#pragma unroll
            for (int r = 0; r < 8; r++) {
                bool p = lexgt(tv[r], ti[r], pv[7 - r], pi[7 - r]);
                L[r]  = p ? tv[r] : pv[7 - r];
                Li[r] = p ? ti[r] : pi[7 - r];
            }
#define LCE(i, j)                                                   \
            {                                                       \
                if (lexgt(L[j], Li[j], L[i], Li[i])) {              \
                    float fv = L[i]; L[i] = L[j]; L[j] = fv;        \
                    int   fi = Li[i]; Li[i] = Li[j]; Li[j] = fi;    \
                }                                                   \
            }
            LCE(0, 4) LCE(1, 5) LCE(2, 6) LCE(3, 7)
            LCE(0, 2) LCE(1, 3) LCE(4, 6) LCE(5, 7)
            LCE(0, 1) LCE(2, 3) LCE(4, 5) LCE(6, 7)
#undef LCE
#pragma unroll
            for (int r = 0; r < 8; r++) { tv[r] = L[r]; ti[r] = Li[r]; }
        }
#pragma unroll
        for (int r = 0; r < 8; r++) idx[r] = ti[r];
    } else {
        // Overflow fallback: exact serial scan on lane 0 (never on this data).
        float tv[8]; int ti[8];
#pragma unroll
        for (int r = 0; r < 8; r++) { tv[r] = -FLT_MAX; ti[r] = 0x7FFFFFFF; }
        if (lane == 0) {
            const float* xrow = x + (size_t)n * QD;
            for (int i = 0; i < QD; i++) {
                float v = xrow[i];
                if (lexgt(v, i, tv[7], ti[7])) {
                    tv[7] = v; ti[7] = i;
#pragma unroll
                    for (int p = 7; p > 0; p--) {
                        if (lexgt(tv[p], ti[p], tv[p - 1], ti[p - 1])) {
                            float fv = tv[p]; tv[p] = tv[p - 1]; tv[p - 1] = fv;
                            int   fi = ti[p]; ti[p] = ti[p - 1]; ti[p - 1] = fi;
                        }
                    }
                }
            }
        }
#pragma unroll
        for (int r = 0; r < 8; r++) idx[r] = __shfl_sync(0xffffffffu, ti[r], 0);
    }

    // ---- Phase 5: out[n, :] = sum_{j<8} wT[idx_j, :] in descending-value
    // order (== jax's summation order). 4 float4 segments per lane.
    const float4* wT4 = reinterpret_cast<const float4*>(g_wT);
    float4* out4 = reinterpret_cast<float4*>(out);
#pragma unroll
    for (int seg = 0; seg < 4; seg++) {
        float4 acc = make_float4(0.f, 0.f, 0.f, 0.f);
#pragma unroll
        for (int r = 0; r < 8; r++) {
            float4 wv = wT4[(size_t)idx[r] * (ED / 4) + seg * 32 + lane];
            acc.x += wv.x; acc.y += wv.y; acc.z += wv.z; acc.w += wv.w;
        }
        out4[(size_t)n * (ED / 4) + seg * 32 + lane] = acc;
    }
}

// ---------------------------------------------------------------------------
extern "C" void kernel_launch(void* const* d_in, const int* in_sizes, int n_in,
                              void* d_out, int out_size) {
    const float* x = (const float*)d_in[0];   // [NT, QD] f32
    const float* w = (const float*)d_in[1];   // [ED, QD] f32
    float* out = (float*)d_out;               // [NT, ED] f32

    dim3 tb(32, 8);
    dim3 tg(QD / 32, ED / 32);
    transpose_kernel<<<tg, tb>>>(w);
    topk_gather_kernel<<<NT / WPB, 32 * WPB>>>(x, out);
}